// round 1
// baseline (speedup 1.0000x reference)
#include <cuda_runtime.h>
#include <cuda_bf16.h>
#include <cstdint>

// Problem constants (fixed by the dataset)
#define NN 100000
#define NE 1600000
#define DF 128
#define DH 64

// ---------------- device scratch (no allocations allowed) ----------------
__device__ float  g_deg[NN];            // degree -> overwritten with d^{-1/2}
__device__ float4 g_h1 [NN * (DH/4)];   // x @ W1, [N,64] as float4
__device__ float4 g_agg1[NN * (DH/4)];  // scatter target, [N,64] as float4
__device__ float  g_norm[NE];           // per-edge symmetric norm
__device__ float  g_h2 [NN];            // relu(layer1) @ W2, scalar per node

// ---------------- K0: init deg=1 (self loop), zero agg1 and out ----------
__global__ void k_init(float* __restrict__ out) {
    int i = blockIdx.x * blockDim.x + threadIdx.x;
    if (i < NN * (DH/4)) g_agg1[i] = make_float4(0.f, 0.f, 0.f, 0.f);
    if (i < NN) { g_deg[i] = 1.0f; out[i] = 0.0f; }
}

// ---------------- K1: deg[col] += w --------------------------------------
__global__ void k_deg(const int* __restrict__ cols, const float* __restrict__ ew) {
    int e = blockIdx.x * blockDim.x + threadIdx.x;
    if (e >= NE) return;
    atomicAdd(&g_deg[cols[e]], ew[e]);
}

// ---------------- K2: dinv = rsqrt(deg) (deg >= 1 always) ----------------
__global__ void k_dinv() {
    int i = blockIdx.x * blockDim.x + threadIdx.x;
    if (i < NN) g_deg[i] = rsqrtf(g_deg[i]);
}

// ---------------- K3: norm[e] = dinv[row]*w*dinv[col] --------------------
__global__ void k_norm(const int* __restrict__ rows, const int* __restrict__ cols,
                       const float* __restrict__ ew) {
    int e = blockIdx.x * blockDim.x + threadIdx.x;
    if (e >= NE) return;
    g_norm[e] = g_deg[rows[e]] * ew[e] * g_deg[cols[e]];
}

// ---------------- K4: h1 = x @ W1 (128 -> 64) ----------------------------
// 128 threads/block, 1 row per thread, W1 staged in smem as float4.
__global__ void __launch_bounds__(128) k_gemm1(const float* __restrict__ x,
                                               const float* __restrict__ W1) {
    __shared__ float4 Ws[DF * (DH/4)];   // 128 rows x 16 float4 = 32KB
    int tid = threadIdx.x;
    for (int i = tid; i < DF * (DH/4); i += 128)
        Ws[i] = reinterpret_cast<const float4*>(W1)[i];
    __syncthreads();

    int row = blockIdx.x * 128 + tid;
    if (row >= NN) return;

    float acc[DH];
    #pragma unroll
    for (int j = 0; j < DH; j++) acc[j] = 0.f;

    const float4* xr = reinterpret_cast<const float4*>(x + (size_t)row * DF);
    #pragma unroll 2
    for (int k4 = 0; k4 < DF / 4; k4++) {
        float4 xv = __ldg(&xr[k4]);
        #pragma unroll
        for (int kk = 0; kk < 4; kk++) {
            float xs = (kk == 0) ? xv.x : (kk == 1) ? xv.y : (kk == 2) ? xv.z : xv.w;
            const float4* wrow = &Ws[(k4 * 4 + kk) * (DH/4)];
            #pragma unroll
            for (int j4 = 0; j4 < DH/4; j4++) {
                float4 w = wrow[j4];
                acc[j4*4+0] += xs * w.x;
                acc[j4*4+1] += xs * w.y;
                acc[j4*4+2] += xs * w.z;
                acc[j4*4+3] += xs * w.w;
            }
        }
    }
    float4* hr = &g_h1[(size_t)row * (DH/4)];
    #pragma unroll
    for (int j4 = 0; j4 < DH/4; j4++)
        hr[j4] = make_float4(acc[j4*4+0], acc[j4*4+1], acc[j4*4+2], acc[j4*4+3]);
}

// ---------------- K5: scatter layer-1 messages (vector RED) --------------
// 16 threads per edge; each handles one float4 of the 64-wide message.
__global__ void k_scatter1(const int* __restrict__ rows, const int* __restrict__ cols) {
    long long gid = (long long)blockIdx.x * blockDim.x + threadIdx.x;
    if (gid >= (long long)NE * 16) return;
    int e = (int)(gid >> 4);
    int q = (int)(gid & 15);
    int r = __ldg(&rows[e]);
    int c = __ldg(&cols[e]);
    float nrm = __ldg(&g_norm[e]);
    float4 hv = g_h1[(size_t)r * 16 + q];
    float4 m = make_float4(hv.x * nrm, hv.y * nrm, hv.z * nrm, hv.w * nrm);
    float4* dst = &g_agg1[(size_t)c * 16 + q];
    asm volatile("red.global.add.v4.f32 [%0], {%1,%2,%3,%4};"
                 :: "l"(dst), "f"(m.x), "f"(m.y), "f"(m.z), "f"(m.w) : "memory");
}

// ---------------- K6: h2[n] = relu(agg + self + b1) . W2 -----------------
// one warp per node
__global__ void __launch_bounds__(256) k_fin1(const float* __restrict__ b1,
                                              const float* __restrict__ W2) {
    int warp = (blockIdx.x * blockDim.x + threadIdx.x) >> 5;
    int lane = threadIdx.x & 31;
    if (warp >= NN) return;
    float d = g_deg[warp];
    float d2 = d * d;
    const float* agg = reinterpret_cast<const float*>(&g_agg1[(size_t)warp * 16]);
    const float* h1v = reinterpret_cast<const float*>(&g_h1 [(size_t)warp * 16]);
    float s = 0.f;
    #pragma unroll
    for (int half = 0; half < 2; half++) {
        int j = lane + half * 32;
        float v = agg[j] + h1v[j] * d2 + __ldg(&b1[j]);
        v = fmaxf(v, 0.f);
        s += v * __ldg(&W2[j]);
    }
    #pragma unroll
    for (int off = 16; off > 0; off >>= 1)
        s += __shfl_xor_sync(0xffffffffu, s, off);
    if (lane == 0) g_h2[warp] = s;
}

// ---------------- K7: scatter layer-2 (scalar RED) -----------------------
__global__ void k_scatter2(const int* __restrict__ rows, const int* __restrict__ cols,
                           float* __restrict__ out) {
    int e = blockIdx.x * blockDim.x + threadIdx.x;
    if (e >= NE) return;
    int r = __ldg(&rows[e]);
    int c = __ldg(&cols[e]);
    atomicAdd(&out[c], g_h2[r] * g_norm[e]);
}

// ---------------- K8: out[n] += self + b2 --------------------------------
__global__ void k_fin2(float* __restrict__ out, const float* __restrict__ b2) {
    int n = blockIdx.x * blockDim.x + threadIdx.x;
    if (n >= NN) return;
    float d = g_deg[n];
    out[n] += g_h2[n] * d * d + __ldg(&b2[0]);
}

// ---------------- launch ---------------------------------------------------
extern "C" void kernel_launch(void* const* d_in, const int* in_sizes, int n_in,
                              void* d_out, int out_size) {
    const float* x  = (const float*)d_in[0];
    const int*   ei = (const int*)  d_in[1];
    const float* ew = (const float*)d_in[2];
    const float* W1 = (const float*)d_in[3];
    const float* b1 = (const float*)d_in[4];
    const float* W2 = (const float*)d_in[5];
    const float* b2 = (const float*)d_in[6];
    float* out = (float*)d_out;

    const int* rows = ei;        // edge_index[0] = sources (gather)
    const int* cols = ei + NE;   // edge_index[1] = targets (scatter)

    k_init<<<(NN * (DH/4) + 255) / 256, 256>>>(out);
    k_deg <<<(NE + 255) / 256, 256>>>(cols, ew);
    k_dinv<<<(NN + 255) / 256, 256>>>();
    k_norm<<<(NE + 255) / 256, 256>>>(rows, cols, ew);
    k_gemm1<<<(NN + 127) / 128, 128>>>(x, W1);
    {
        long long total = (long long)NE * 16;
        int blocks = (int)((total + 255) / 256);
        k_scatter1<<<blocks, 256>>>(rows, cols);
    }
    k_fin1<<<(NN * 32 + 255) / 256, 256>>>(b1, W2);
    k_scatter2<<<(NE + 255) / 256, 256>>>(rows, cols, out);
    k_fin2<<<(NN + 255) / 256, 256>>>(out, b2);
}

// round 2
// speedup vs baseline: 1.6630x; 1.6630x over previous
#include <cuda_runtime.h>
#include <cuda_bf16.h>
#include <cstdint>

#define NN 100000
#define NE 1600000
#define DF 128
#define DH 64
#define NBLK 98   // ceil((NN+1)/1024)

// ---------------- device scratch ----------------
__device__ float     g_deg[NN];              // weighted degree -> d^{-1/2}
__device__ unsigned  g_cnt[NN];              // in-edge counts
__device__ unsigned  g_off[NN + 1];          // CSR offsets (by target)
__device__ unsigned  g_cur[NN];              // fill cursors
__device__ unsigned  g_bsum[NBLK];           // scan block sums
__device__ unsigned  g_bpre[NBLK];           // scanned block sums
__device__ int2      g_edge[NE];             // (src row, norm as bits)
__device__ float4    g_h1[NN * (DH / 4)];    // x @ W1  [N,64]
__device__ float     g_h2[NN];               // relu(layer1) . W2

// ---------------- K0: init ----------------
__global__ void k_init() {
    int i = blockIdx.x * blockDim.x + threadIdx.x;
    if (i < NN) { g_deg[i] = 1.0f; g_cnt[i] = 0u; }
}

// ---------------- K1: weighted degree + in-edge counts ----------------
__global__ void k_deg(const int* __restrict__ cols, const float* __restrict__ ew) {
    int e = blockIdx.x * blockDim.x + threadIdx.x;
    if (e >= NE) return;
    int c = cols[e];
    atomicAdd(&g_deg[c], ew[e]);
    atomicAdd(&g_cnt[c], 1u);
}

// ---------------- K2: dinv = rsqrt(deg)  (deg >= 1 always) ----------------
__global__ void k_dinv() {
    int i = blockIdx.x * blockDim.x + threadIdx.x;
    if (i < NN) g_deg[i] = rsqrtf(g_deg[i]);
}

// ---------------- K3a/b/c: exclusive scan of g_cnt into g_off ----------------
__global__ void __launch_bounds__(1024) k_scan1() {
    __shared__ unsigned s[1024];
    int t = threadIdx.x;
    int i = blockIdx.x * 1024 + t;
    unsigned v = (i < NN) ? g_cnt[i] : 0u;
    s[t] = v;
    __syncthreads();
    #pragma unroll
    for (int off = 1; off < 1024; off <<= 1) {
        unsigned u = (t >= off) ? s[t - off] : 0u;
        __syncthreads();
        s[t] += u;
        __syncthreads();
    }
    if (i <= NN) g_off[i] = s[t] - v;      // exclusive
    if (t == 1023) g_bsum[blockIdx.x] = s[1023];
}

__global__ void __launch_bounds__(128) k_scan2() {
    __shared__ unsigned s[128];
    int t = threadIdx.x;
    unsigned v = (t < NBLK) ? g_bsum[t] : 0u;
    s[t] = v;
    __syncthreads();
    #pragma unroll
    for (int off = 1; off < 128; off <<= 1) {
        unsigned u = (t >= off) ? s[t - off] : 0u;
        __syncthreads();
        s[t] += u;
        __syncthreads();
    }
    if (t < NBLK) g_bpre[t] = s[t] - v;    // exclusive
}

__global__ void k_scan3() {
    int i = blockIdx.x * blockDim.x + threadIdx.x;
    if (i > NN) return;
    unsigned o = g_off[i] + g_bpre[i >> 10];
    g_off[i] = o;
    if (i < NN) g_cur[i] = o;
}

// ---------------- K4: fill CSR with (row, norm) ----------------
__global__ void k_fill(const int* __restrict__ rows, const int* __restrict__ cols,
                       const float* __restrict__ ew) {
    int e = blockIdx.x * blockDim.x + threadIdx.x;
    if (e >= NE) return;
    int r = rows[e], c = cols[e];
    float nm = g_deg[r] * ew[e] * g_deg[c];
    unsigned pos = atomicAdd(&g_cur[c], 1u);
    g_edge[pos] = make_int2(r, __float_as_int(nm));
}

// ---------------- K5: h1 = x @ W1 via packed f32x2 FMA ----------------
__global__ void __launch_bounds__(128) k_gemm1(const float* __restrict__ x,
                                               const float* __restrict__ W1) {
    __shared__ unsigned long long Ws[DF * (DH / 2)];  // 128 x 32 pairs = 32KB
    int tid = threadIdx.x;
    const unsigned long long* W64 = reinterpret_cast<const unsigned long long*>(W1);
    for (int i = tid; i < DF * (DH / 2); i += 128) Ws[i] = W64[i];
    __syncthreads();

    int row = blockIdx.x * 128 + tid;
    if (row >= NN) return;

    unsigned long long acc[DH / 2];
    #pragma unroll
    for (int j = 0; j < DH / 2; j++) acc[j] = 0ULL;   // two packed +0.0f

    const float4* xr = reinterpret_cast<const float4*>(x + (size_t)row * DF);
    #pragma unroll 1
    for (int k4 = 0; k4 < DF / 4; k4++) {
        float4 xv = __ldg(&xr[k4]);
        float xs4[4] = {xv.x, xv.y, xv.z, xv.w};
        #pragma unroll
        for (int kk = 0; kk < 4; kk++) {
            unsigned long long xp;
            unsigned xb = __float_as_uint(xs4[kk]);
            asm("mov.b64 %0, {%1, %1};" : "=l"(xp) : "r"(xb));
            const unsigned long long* wr = &Ws[(k4 * 4 + kk) * (DH / 2)];
            #pragma unroll
            for (int j = 0; j < DH / 2; j++) {
                asm("fma.rn.f32x2 %0, %1, %2, %0;" : "+l"(acc[j]) : "l"(xp), "l"(wr[j]));
            }
        }
    }
    unsigned long long* hr =
        reinterpret_cast<unsigned long long*>(&g_h1[(size_t)row * (DH / 4)]);
    #pragma unroll
    for (int j = 0; j < DH / 2; j++) hr[j] = acc[j];
}

// ---------------- K6: gather layer-1 + bias + relu + dot W2 -> h2 ----------
// One warp per node; lane covers features (2*lane, 2*lane+1).
__global__ void __launch_bounds__(256) k_gather1(const float* __restrict__ b1,
                                                 const float* __restrict__ W2) {
    int warp = (blockIdx.x * blockDim.x + threadIdx.x) >> 5;
    int lane = threadIdx.x & 31;
    if (warp >= NN) return;

    unsigned s0 = g_off[warp], s1 = g_off[warp + 1];
    const float2* h1f2 = reinterpret_cast<const float2*>(g_h1);

    float ax = 0.f, ay = 0.f;
    unsigned e = s0;
    for (; e + 1 < s1; e += 2) {
        int2 ed0 = g_edge[e];
        int2 ed1 = g_edge[e + 1];
        float2 h0 = h1f2[(size_t)ed0.x * 32 + lane];
        float2 h1v = h1f2[(size_t)ed1.x * 32 + lane];
        float n0 = __int_as_float(ed0.y), n1 = __int_as_float(ed1.y);
        ax = fmaf(n0, h0.x, ax);  ay = fmaf(n0, h0.y, ay);
        ax = fmaf(n1, h1v.x, ax); ay = fmaf(n1, h1v.y, ay);
    }
    if (e < s1) {
        int2 ed = g_edge[e];
        float2 h0 = h1f2[(size_t)ed.x * 32 + lane];
        float nm = __int_as_float(ed.y);
        ax = fmaf(nm, h0.x, ax);  ay = fmaf(nm, h0.y, ay);
    }

    // self loop: norm = dinv[n]^2
    float d = g_deg[warp];
    float d2 = d * d;
    float2 hs = h1f2[(size_t)warp * 32 + lane];
    ax = fmaf(d2, hs.x, ax);  ay = fmaf(d2, hs.y, ay);

    float2 bb = reinterpret_cast<const float2*>(b1)[lane];
    float v0 = fmaxf(ax + bb.x, 0.f);
    float v1 = fmaxf(ay + bb.y, 0.f);
    float2 w = reinterpret_cast<const float2*>(W2)[lane];
    float s = v0 * w.x + v1 * w.y;
    #pragma unroll
    for (int off = 16; off > 0; off >>= 1)
        s += __shfl_xor_sync(0xffffffffu, s, off);
    if (lane == 0) g_h2[warp] = s;
}

// ---------------- K7: gather layer-2 -> out ----------------
// One warp per node; lanes parallel over edges.
__global__ void __launch_bounds__(256) k_gather2(float* __restrict__ out,
                                                 const float* __restrict__ b2) {
    int warp = (blockIdx.x * blockDim.x + threadIdx.x) >> 5;
    int lane = threadIdx.x & 31;
    if (warp >= NN) return;
    unsigned s0 = g_off[warp], s1 = g_off[warp + 1];
    float acc = 0.f;
    for (unsigned e = s0 + lane; e < s1; e += 32) {
        int2 ed = g_edge[e];
        acc = fmaf(__int_as_float(ed.y), g_h2[ed.x], acc);
    }
    #pragma unroll
    for (int off = 16; off > 0; off >>= 1)
        acc += __shfl_xor_sync(0xffffffffu, acc, off);
    if (lane == 0) {
        float d = g_deg[warp];
        out[warp] = acc + d * d * g_h2[warp] + __ldg(&b2[0]);
    }
}

// ---------------- launch ----------------
extern "C" void kernel_launch(void* const* d_in, const int* in_sizes, int n_in,
                              void* d_out, int out_size) {
    const float* x  = (const float*)d_in[0];
    const int*   ei = (const int*)  d_in[1];
    const float* ew = (const float*)d_in[2];
    const float* W1 = (const float*)d_in[3];
    const float* b1 = (const float*)d_in[4];
    const float* W2 = (const float*)d_in[5];
    const float* b2 = (const float*)d_in[6];
    float* out = (float*)d_out;

    const int* rows = ei;        // sources (gather)
    const int* cols = ei + NE;   // targets (scatter -> CSR key)

    k_init <<<(NN + 255) / 256, 256>>>();
    k_deg  <<<(NE + 255) / 256, 256>>>(cols, ew);
    k_dinv <<<(NN + 255) / 256, 256>>>();
    k_scan1<<<NBLK, 1024>>>();
    k_scan2<<<1, 128>>>();
    k_scan3<<<(NN + 1 + 255) / 256, 256>>>();
    k_fill <<<(NE + 255) / 256, 256>>>(rows, cols, ew);
    k_gemm1<<<(NN + 127) / 128, 128>>>(x, W1);
    k_gather1<<<(NN * 32 + 255) / 256, 256>>>(b1, W2);
    k_gather2<<<(NN * 32 + 255) / 256, 256>>>(out, b2);
}

// round 3
// speedup vs baseline: 1.9689x; 1.1840x over previous
#include <cuda_runtime.h>
#include <cuda_bf16.h>
#include <cstdint>

#define NN 100000
#define NE 1600000
#define DF 128
#define DH 64
#define NBLK 98   // ceil((NN+1)/1024)

// ---------------- device scratch ----------------
__device__ float     g_deg[NN];              // weighted degree -> d^{-1/2}
__device__ unsigned  g_cnt[NN];              // in-edge counts
__device__ unsigned  g_off[NN + 1];          // CSR offsets (by target)
__device__ unsigned  g_cur[NN];              // fill cursors
__device__ unsigned  g_bsum[NBLK];           // scan block sums
__device__ unsigned  g_bpre[NBLK];           // scanned block sums
__device__ int2      g_edge[NE];             // (src row, norm as bits)
__device__ float4    g_h1[NN * (DH / 4)];    // x @ W1  [N,64]
__device__ float     g_h2[NN];               // relu(layer1) . W2

// ---------------- K0: init ----------------
__global__ void k_init() {
    int i = blockIdx.x * blockDim.x + threadIdx.x;
    if (i < NN) { g_deg[i] = 1.0f; g_cnt[i] = 0u; }
}

// ---------------- K1: weighted degree + in-edge counts ----------------
__global__ void k_deg(const int* __restrict__ cols, const float* __restrict__ ew) {
    int e = blockIdx.x * blockDim.x + threadIdx.x;
    if (e >= NE) return;
    int c = cols[e];
    atomicAdd(&g_deg[c], ew[e]);
    atomicAdd(&g_cnt[c], 1u);
}

// ---------------- K2a/b/c: exclusive scan of g_cnt into g_off --------------
__global__ void __launch_bounds__(1024) k_scan1() {
    __shared__ unsigned s[1024];
    int t = threadIdx.x;
    int i = blockIdx.x * 1024 + t;
    unsigned v = (i < NN) ? g_cnt[i] : 0u;
    s[t] = v;
    __syncthreads();
    #pragma unroll
    for (int off = 1; off < 1024; off <<= 1) {
        unsigned u = (t >= off) ? s[t - off] : 0u;
        __syncthreads();
        s[t] += u;
        __syncthreads();
    }
    if (i <= NN) g_off[i] = s[t] - v;      // exclusive
    if (t == 1023) g_bsum[blockIdx.x] = s[1023];
}

__global__ void __launch_bounds__(128) k_scan2() {
    __shared__ unsigned s[128];
    int t = threadIdx.x;
    unsigned v = (t < NBLK) ? g_bsum[t] : 0u;
    s[t] = v;
    __syncthreads();
    #pragma unroll
    for (int off = 1; off < 128; off <<= 1) {
        unsigned u = (t >= off) ? s[t - off] : 0u;
        __syncthreads();
        s[t] += u;
        __syncthreads();
    }
    if (t < NBLK) g_bpre[t] = s[t] - v;    // exclusive
}

// scan fixup + dinv (both elementwise, both depend only on k_deg/scan2)
__global__ void k_scan3() {
    int i = blockIdx.x * blockDim.x + threadIdx.x;
    if (i > NN) return;
    unsigned o = g_off[i] + g_bpre[i >> 10];
    g_off[i] = o;
    if (i < NN) {
        g_cur[i] = o;
        g_deg[i] = rsqrtf(g_deg[i]);
    }
}

// ---------------- K3: fill CSR with (row, norm) ----------------
__global__ void k_fill(const int* __restrict__ rows, const int* __restrict__ cols,
                       const float* __restrict__ ew) {
    int e = blockIdx.x * blockDim.x + threadIdx.x;
    if (e >= NE) return;
    int r = rows[e], c = cols[e];
    float nm = g_deg[r] * ew[e] * g_deg[c];
    unsigned pos = atomicAdd(&g_cur[c], 1u);
    g_edge[pos] = make_int2(r, __float_as_int(nm));
}

// ---------------- K4: h1 = x @ W1 via packed f32x2 FMA ----------------
__global__ void __launch_bounds__(128) k_gemm1(const float* __restrict__ x,
                                               const float* __restrict__ W1) {
    __shared__ unsigned long long Ws[DF * (DH / 2)];  // 128 x 32 pairs = 32KB
    int tid = threadIdx.x;
    const unsigned long long* W64 = reinterpret_cast<const unsigned long long*>(W1);
    for (int i = tid; i < DF * (DH / 2); i += 128) Ws[i] = W64[i];
    __syncthreads();

    int row = blockIdx.x * 128 + tid;
    if (row >= NN) return;

    unsigned long long acc[DH / 2];
    #pragma unroll
    for (int j = 0; j < DH / 2; j++) acc[j] = 0ULL;

    const float4* xr = reinterpret_cast<const float4*>(x + (size_t)row * DF);
    #pragma unroll 1
    for (int k4 = 0; k4 < DF / 4; k4++) {
        float4 xv = __ldg(&xr[k4]);
        float xs4[4] = {xv.x, xv.y, xv.z, xv.w};
        #pragma unroll
        for (int kk = 0; kk < 4; kk++) {
            unsigned long long xp;
            unsigned xb = __float_as_uint(xs4[kk]);
            asm("mov.b64 %0, {%1, %1};" : "=l"(xp) : "r"(xb));
            const unsigned long long* wr = &Ws[(k4 * 4 + kk) * (DH / 2)];
            #pragma unroll
            for (int j = 0; j < DH / 2; j++) {
                asm("fma.rn.f32x2 %0, %1, %2, %0;" : "+l"(acc[j]) : "l"(xp), "l"(wr[j]));
            }
        }
    }
    unsigned long long* hr =
        reinterpret_cast<unsigned long long*>(&g_h1[(size_t)row * (DH / 4)]);
    #pragma unroll
    for (int j = 0; j < DH / 2; j++) hr[j] = acc[j];
}

// ---------------- K5: gather layer-1 + bias + relu + dot W2 -> h2 ----------
// One warp per node. Edge records loaded 32-wide (coalesced), broadcast via
// SHFL.IDX so the h1 gathers form an independent, deeply pipelined stream.
__global__ void __launch_bounds__(256) k_gather1(const float* __restrict__ b1,
                                                 const float* __restrict__ W2) {
    int warp = (blockIdx.x * blockDim.x + threadIdx.x) >> 5;
    int lane = threadIdx.x & 31;
    if (warp >= NN) return;

    unsigned s0 = g_off[warp], s1 = g_off[warp + 1];
    const float2* h1f2 = reinterpret_cast<const float2*>(g_h1);

    float ax = 0.f, ay = 0.f;
    for (unsigned base = s0; base < s1; base += 32) {
        int m = min(32, (int)(s1 - base));
        int2 ed = make_int2(0, 0);
        if (lane < m) ed = g_edge[base + lane];
        #pragma unroll 4
        for (int j = 0; j < m; j++) {
            int   rj = __shfl_sync(0xffffffffu, ed.x, j);
            float nj = __int_as_float(__shfl_sync(0xffffffffu, ed.y, j));
            float2 h = h1f2[(size_t)rj * 32 + lane];
            ax = fmaf(nj, h.x, ax);
            ay = fmaf(nj, h.y, ay);
        }
    }

    // self loop: norm = dinv[n]^2
    float d = g_deg[warp];
    float d2 = d * d;
    float2 hs = h1f2[(size_t)warp * 32 + lane];
    ax = fmaf(d2, hs.x, ax);
    ay = fmaf(d2, hs.y, ay);

    float2 bb = reinterpret_cast<const float2*>(b1)[lane];
    float v0 = fmaxf(ax + bb.x, 0.f);
    float v1 = fmaxf(ay + bb.y, 0.f);
    float2 w = reinterpret_cast<const float2*>(W2)[lane];
    float s = v0 * w.x + v1 * w.y;
    #pragma unroll
    for (int off = 16; off > 0; off >>= 1)
        s += __shfl_xor_sync(0xffffffffu, s, off);
    if (lane == 0) g_h2[warp] = s;
}

// ---------------- K6: gather layer-2 -> out ----------------
__global__ void __launch_bounds__(256) k_gather2(float* __restrict__ out,
                                                 const float* __restrict__ b2) {
    int warp = (blockIdx.x * blockDim.x + threadIdx.x) >> 5;
    int lane = threadIdx.x & 31;
    if (warp >= NN) return;
    unsigned s0 = g_off[warp], s1 = g_off[warp + 1];
    float acc = 0.f;
    for (unsigned e = s0 + lane; e < s1; e += 32) {
        int2 ed = g_edge[e];
        acc = fmaf(__int_as_float(ed.y), g_h2[ed.x], acc);
    }
    #pragma unroll
    for (int off = 16; off > 0; off >>= 1)
        acc += __shfl_xor_sync(0xffffffffu, acc, off);
    if (lane == 0) {
        float d = g_deg[warp];
        out[warp] = acc + d * d * g_h2[warp] + __ldg(&b2[0]);
    }
}

// ---------------- launch ----------------
extern "C" void kernel_launch(void* const* d_in, const int* in_sizes, int n_in,
                              void* d_out, int out_size) {
    const float* x  = (const float*)d_in[0];
    const int*   ei = (const int*)  d_in[1];
    const float* ew = (const float*)d_in[2];
    const float* W1 = (const float*)d_in[3];
    const float* b1 = (const float*)d_in[4];
    const float* W2 = (const float*)d_in[5];
    const float* b2 = (const float*)d_in[6];
    float* out = (float*)d_out;

    const int* rows = ei;        // sources (gather)
    const int* cols = ei + NE;   // targets (CSR key)

    // One-time side-stream/event setup (host resources only, no device mem).
    // Created during the (non-captured) correctness call; reused at capture.
    static cudaStream_t s2 = nullptr;
    static cudaEvent_t evFork = nullptr, evJoin = nullptr;
    if (s2 == nullptr) {
        cudaStreamCreateWithFlags(&s2, cudaStreamNonBlocking);
        cudaEventCreateWithFlags(&evFork, cudaEventDisableTiming);
        cudaEventCreateWithFlags(&evJoin, cudaEventDisableTiming);
    }

    // Fork: GEMM1 (FMA-bound) overlaps the CSR build (LTS/atomic-bound).
    cudaEventRecord(evFork, 0);
    cudaStreamWaitEvent(s2, evFork, 0);
    k_gemm1<<<(NN + 127) / 128, 128, 0, s2>>>(x, W1);
    cudaEventRecord(evJoin, s2);

    // Main chain: CSR build
    k_init <<<(NN + 255) / 256, 256>>>();
    k_deg  <<<(NE + 255) / 256, 256>>>(cols, ew);
    k_scan1<<<NBLK, 1024>>>();
    k_scan2<<<1, 128>>>();
    k_scan3<<<(NN + 1 + 255) / 256, 256>>>();
    k_fill <<<(NE + 255) / 256, 256>>>(rows, cols, ew);

    // Join, then the two gather layers.
    cudaStreamWaitEvent(0, evJoin, 0);
    k_gather1<<<(NN * 32 + 255) / 256, 256>>>(b1, W2);
    k_gather2<<<(NN * 32 + 255) / 256, 256>>>(out, b2);
}

// round 5
// speedup vs baseline: 2.0715x; 1.0521x over previous
#include <cuda_runtime.h>
#include <cuda_fp16.h>
#include <cstdint>

#define NN 100000
#define NE 1600000
#define DF 128
#define DH 64
#define NBLK 98   // ceil((NN+1)/1024)

// ---------------- device scratch ----------------
__device__ unsigned long long g_pack[NN];    // hi16: in-count, lo48: ew * 2^32
__device__ float     g_deg[NN];              // d^{-1/2}
__device__ unsigned  g_off[NN + 1];          // CSR offsets (by target)
__device__ unsigned  g_cur[NN];              // fill cursors
__device__ unsigned  g_bsum[NBLK];           // scan block sums
__device__ unsigned  g_bpre[NBLK];           // scanned block sums
__device__ int2      g_edge[NE];             // (src row, norm as bits)
__device__ __half2   g_h1[NN * (DH / 2)];    // x @ W1, [N,64] fp16, 128B/node
__device__ float     g_h2[NN];               // relu(layer1) . W2

// ---------------- K0: init ----------------
__global__ void k_init() {
    int i = blockIdx.x * blockDim.x + threadIdx.x;
    if (i < NN) g_pack[i] = 0ULL;
}

// ---------------- K1: packed degree+count atomic ----------------
__global__ void k_deg(const int* __restrict__ cols, const float* __restrict__ ew) {
    int e = blockIdx.x * blockDim.x + threadIdx.x;
    if (e >= NE) return;
    int c = cols[e];
    unsigned long long v =
        (1ULL << 48) | (unsigned long long)((double)ew[e] * 4294967296.0);
    atomicAdd(&g_pack[c], v);
}

// ---------------- K2a/b/c: exclusive scan of counts into g_off -------------
__global__ void __launch_bounds__(1024) k_scan1() {
    __shared__ unsigned s[1024];
    int t = threadIdx.x;
    int i = blockIdx.x * 1024 + t;
    unsigned v = (i < NN) ? (unsigned)(g_pack[i] >> 48) : 0u;
    s[t] = v;
    __syncthreads();
    #pragma unroll
    for (int off = 1; off < 1024; off <<= 1) {
        unsigned u = (t >= off) ? s[t - off] : 0u;
        __syncthreads();
        s[t] += u;
        __syncthreads();
    }
    if (i <= NN) g_off[i] = s[t] - v;      // exclusive
    if (t == 1023) g_bsum[blockIdx.x] = s[1023];
}

__global__ void __launch_bounds__(128) k_scan2() {
    __shared__ unsigned s[128];
    int t = threadIdx.x;
    unsigned v = (t < NBLK) ? g_bsum[t] : 0u;
    s[t] = v;
    __syncthreads();
    #pragma unroll
    for (int off = 1; off < 128; off <<= 1) {
        unsigned u = (t >= off) ? s[t - off] : 0u;
        __syncthreads();
        s[t] += u;
        __syncthreads();
    }
    if (t < NBLK) g_bpre[t] = s[t] - v;    // exclusive
}

// scan fixup + dinv
__global__ void k_scan3() {
    int i = blockIdx.x * blockDim.x + threadIdx.x;
    if (i > NN) return;
    unsigned o = g_off[i] + g_bpre[i >> 10];
    g_off[i] = o;
    if (i < NN) {
        g_cur[i] = o;
        double dsum = (double)(g_pack[i] & 0xFFFFFFFFFFFFULL) * (1.0 / 4294967296.0);
        g_deg[i] = rsqrtf((float)(1.0 + dsum));   // +1 = self loop
    }
}

// ---------------- K3: fill CSR with (row, norm) ----------------
__global__ void k_fill(const int* __restrict__ rows, const int* __restrict__ cols,
                       const float* __restrict__ ew) {
    int e = blockIdx.x * blockDim.x + threadIdx.x;
    if (e >= NE) return;
    int r = rows[e], c = cols[e];
    float nm = g_deg[r] * ew[e] * g_deg[c];
    unsigned pos = atomicAdd(&g_cur[c], 1u);
    g_edge[pos] = make_int2(r, __float_as_int(nm));
}

// ---------------- K4: h1 = x @ W1, fp32 accum -> fp16 store ----------------
__global__ void __launch_bounds__(128) k_gemm1(const float* __restrict__ x,
                                               const float* __restrict__ W1) {
    __shared__ unsigned long long Ws[DF * (DH / 2)];  // 32KB
    int tid = threadIdx.x;
    const unsigned long long* W64 = reinterpret_cast<const unsigned long long*>(W1);
    for (int i = tid; i < DF * (DH / 2); i += 128) Ws[i] = W64[i];
    __syncthreads();

    int row = blockIdx.x * 128 + tid;
    if (row >= NN) return;

    unsigned long long acc[DH / 2];
    #pragma unroll
    for (int j = 0; j < DH / 2; j++) acc[j] = 0ULL;

    const float4* xr = reinterpret_cast<const float4*>(x + (size_t)row * DF);
    #pragma unroll 1
    for (int k4 = 0; k4 < DF / 4; k4++) {
        float4 xv = __ldg(&xr[k4]);
        float xs4[4] = {xv.x, xv.y, xv.z, xv.w};
        #pragma unroll
        for (int kk = 0; kk < 4; kk++) {
            unsigned long long xp;
            unsigned xb = __float_as_uint(xs4[kk]);
            asm("mov.b64 %0, {%1, %1};" : "=l"(xp) : "r"(xb));
            const unsigned long long* wr = &Ws[(k4 * 4 + kk) * (DH / 2)];
            #pragma unroll
            for (int j = 0; j < DH / 2; j++) {
                asm("fma.rn.f32x2 %0, %1, %2, %0;" : "+l"(acc[j]) : "l"(xp), "l"(wr[j]));
            }
        }
    }
    // convert 32 packed f32x2 -> 32 half2 -> 8 uint4 stores (128B/row)
    uint4* hr = reinterpret_cast<uint4*>(&g_h1[(size_t)row * (DH / 2)]);
    #pragma unroll
    for (int q = 0; q < 8; q++) {
        unsigned p[4];
        #pragma unroll
        for (int k = 0; k < 4; k++) {
            unsigned lo, hi;
            asm("mov.b64 {%0, %1}, %2;" : "=r"(lo), "=r"(hi) : "l"(acc[q * 4 + k]));
            __half2 h = __floats2half2_rn(__uint_as_float(lo), __uint_as_float(hi));
            p[k] = *reinterpret_cast<unsigned*>(&h);
        }
        hr[q] = make_uint4(p[0], p[1], p[2], p[3]);
    }
}

// ---------------- K5: gather layer-1 + bias + relu + dot W2 -> h2 ----------
// One warp per node; lane covers features (2*lane, 2*lane+1) as one half2.
__global__ void __launch_bounds__(256) k_gather1(const float* __restrict__ b1,
                                                 const float* __restrict__ W2) {
    int warp = (blockIdx.x * blockDim.x + threadIdx.x) >> 5;
    int lane = threadIdx.x & 31;
    if (warp >= NN) return;

    unsigned s0 = g_off[warp], s1 = g_off[warp + 1];

    float ax = 0.f, ay = 0.f;
    for (unsigned base = s0; base < s1; base += 32) {
        int m = min(32, (int)(s1 - base));
        int2 ed = make_int2(0, 0);
        if (lane < m) ed = g_edge[base + lane];
        #pragma unroll 4
        for (int j = 0; j < m; j++) {
            int   rj = __shfl_sync(0xffffffffu, ed.x, j);
            float nj = __int_as_float(__shfl_sync(0xffffffffu, ed.y, j));
            float2 h = __half22float2(g_h1[(size_t)rj * 32 + lane]);
            ax = fmaf(nj, h.x, ax);
            ay = fmaf(nj, h.y, ay);
        }
    }

    // self loop: norm = dinv[n]^2
    float d = g_deg[warp];
    float d2 = d * d;
    float2 hs = __half22float2(g_h1[(size_t)warp * 32 + lane]);
    ax = fmaf(d2, hs.x, ax);
    ay = fmaf(d2, hs.y, ay);

    float2 bb = reinterpret_cast<const float2*>(b1)[lane];
    float v0 = fmaxf(ax + bb.x, 0.f);
    float v1 = fmaxf(ay + bb.y, 0.f);
    float2 w = reinterpret_cast<const float2*>(W2)[lane];
    float s = v0 * w.x + v1 * w.y;
    #pragma unroll
    for (int off = 16; off > 0; off >>= 1)
        s += __shfl_xor_sync(0xffffffffu, s, off);
    if (lane == 0) g_h2[warp] = s;
}

// ---------------- K6: gather layer-2 -> out ----------------
__global__ void __launch_bounds__(256) k_gather2(float* __restrict__ out,
                                                 const float* __restrict__ b2) {
    int warp = (blockIdx.x * blockDim.x + threadIdx.x) >> 5;
    int lane = threadIdx.x & 31;
    if (warp >= NN) return;
    unsigned s0 = g_off[warp], s1 = g_off[warp + 1];
    float acc = 0.f;
    for (unsigned e = s0 + lane; e < s1; e += 32) {
        int2 ed = g_edge[e];
        acc = fmaf(__int_as_float(ed.y), g_h2[ed.x], acc);
    }
    #pragma unroll
    for (int off = 16; off > 0; off >>= 1)
        acc += __shfl_xor_sync(0xffffffffu, acc, off);
    if (lane == 0) {
        float d = g_deg[warp];
        out[warp] = acc + d * d * g_h2[warp] + __ldg(&b2[0]);
    }
}

// ---------------- launch ----------------
extern "C" void kernel_launch(void* const* d_in, const int* in_sizes, int n_in,
                              void* d_out, int out_size) {
    const float* x  = (const float*)d_in[0];
    const int*   ei = (const int*)  d_in[1];
    const float* ew = (const float*)d_in[2];
    const float* W1 = (const float*)d_in[3];
    const float* b1 = (const float*)d_in[4];
    const float* W2 = (const float*)d_in[5];
    const float* b2 = (const float*)d_in[6];
    float* out = (float*)d_out;

    const int* rows = ei;        // sources (gather)
    const int* cols = ei + NE;   // targets (CSR key)

    static cudaStream_t s2 = nullptr;
    static cudaEvent_t evFork = nullptr, evJoin = nullptr;
    if (s2 == nullptr) {
        cudaStreamCreateWithFlags(&s2, cudaStreamNonBlocking);
        cudaEventCreateWithFlags(&evFork, cudaEventDisableTiming);
        cudaEventCreateWithFlags(&evJoin, cudaEventDisableTiming);
    }

    // Fork: GEMM1 (FMA-bound) overlaps the CSR build (LTS/atomic-bound).
    cudaEventRecord(evFork, 0);
    cudaStreamWaitEvent(s2, evFork, 0);
    k_gemm1<<<(NN + 127) / 128, 128, 0, s2>>>(x, W1);
    cudaEventRecord(evJoin, s2);

    // Main chain: CSR build
    k_init <<<(NN + 255) / 256, 256>>>();
    k_deg  <<<(NE + 255) / 256, 256>>>(cols, ew);
    k_scan1<<<NBLK, 1024>>>();
    k_scan2<<<1, 128>>>();
    k_scan3<<<(NN + 1 + 255) / 256, 256>>>();
    k_fill <<<(NE + 255) / 256, 256>>>(rows, cols, ew);

    // Join, then the two gather layers.
    cudaStreamWaitEvent(0, evJoin, 0);
    k_gather1<<<(NN * 32 + 255) / 256, 256>>>(b1, W2);
    k_gather2<<<(NN * 32 + 255) / 256, 256>>>(out, b2);
}

// round 8
// speedup vs baseline: 2.1246x; 1.0256x over previous
#include <cuda_runtime.h>
#include <cuda_fp16.h>
#include <cstdint>

#define NN 100000
#define NE 1600000
#define DF 128
#define DH 64
#define STILE 4096
#define NTILES 25   // ceil((NN+1)/STILE); 25 blocks <= 148 SMs -> co-resident

// ---------------- device scratch ----------------
__device__ unsigned long long g_pack[NN];    // hi16: in-count, lo48: ew * 2^32
__device__ float          g_deg[NN];         // d^{-1/2}
__device__ unsigned       g_off[NN + 1];     // CSR offsets (by target)
__device__ unsigned short g_rank[NE];        // edge rank within target node
__device__ unsigned       g_tile[NTILES];    // scan tile sums, bit31 = valid
__device__ int2           g_edge[NE];        // (src row, norm as bits)
__device__ __half2        g_h1[NN * (DH/2)]; // x @ W1, [N,64] fp16, 128B/node
__device__ float          g_h2[NN];          // relu(layer1) . W2

// ---------------- K1: packed degree+count atomic; rank = old count ----------
// Also zeroes g_tile for this replay's scan (kernel-boundary ordered).
__global__ void k_deg(const int* __restrict__ cols, const float* __restrict__ ew) {
    int e = blockIdx.x * blockDim.x + threadIdx.x;
    if (e < NTILES) g_tile[e] = 0u;
    if (e >= NE) return;
    int c = cols[e];
    unsigned long long v =
        (1ULL << 48) | (unsigned long long)((double)ew[e] * 4294967296.0);
    unsigned long long old = atomicAdd(&g_pack[c], v);
    g_rank[e] = (unsigned short)(old >> 48);
}

// ---------------- K2: single-pass scan + dinv + g_pack reset ----------------
// 25 blocks x 512 threads, 8 elements/thread. Publish tile sum with flag,
// parallel lookback over predecessors (all blocks resident -> no deadlock).
__global__ void __launch_bounds__(512) k_scan() {
    __shared__ unsigned warpsum[16];
    __shared__ unsigned s_prefix;
    int t = threadIdx.x;
    int tile = blockIdx.x;
    int base = tile * STILE + t * 8;

    unsigned long long p[8];
    unsigned c[8];
    #pragma unroll
    for (int k = 0; k < 8; k++) {
        int i = base + k;
        p[k] = (i < NN) ? g_pack[i] : 0ULL;
        c[k] = (unsigned)(p[k] >> 48);
    }
    #pragma unroll
    for (int k = 0; k < 8; k++) {
        int i = base + k;
        if (i < NN) g_pack[i] = 0ULL;     // restore invariant for next replay
    }
    unsigned tsum = 0;
    #pragma unroll
    for (int k = 0; k < 8; k++) tsum += c[k];

    unsigned lane = t & 31, wid = t >> 5;
    unsigned scan = tsum;
    #pragma unroll
    for (int off = 1; off < 32; off <<= 1) {
        unsigned v = __shfl_up_sync(0xffffffffu, scan, off);
        if (lane >= off) scan += v;
    }
    if (lane == 31) warpsum[wid] = scan;
    __syncthreads();
    if (wid == 0) {
        unsigned w = (lane < 16) ? warpsum[lane] : 0u;
        #pragma unroll
        for (int off = 1; off < 16; off <<= 1) {
            unsigned v = __shfl_up_sync(0xffffffffu, w, off);
            if (lane >= off) w += v;
        }
        if (lane < 16) warpsum[lane] = w;
    }
    __syncthreads();
    unsigned blocksum = warpsum[15];
    unsigned thr_excl = (scan - tsum) + (wid ? warpsum[wid - 1] : 0u);

    if (t == 0) atomicExch(&g_tile[tile], blocksum | 0x80000000u);

    if (wid == 0) {
        unsigned pre = 0;
        for (int j = (int)lane; j < tile; j += 32) {     // <=1 iter (tile<25)
            unsigned v;
            do { v = atomicOr(&g_tile[j], 0u); } while (!(v & 0x80000000u));
            pre += v & 0x7FFFFFFFu;
        }
        #pragma unroll
        for (int off = 16; off > 0; off >>= 1)
            pre += __shfl_xor_sync(0xffffffffu, pre, off);
        if (lane == 0) s_prefix = pre;
    }
    __syncthreads();

    unsigned excl = s_prefix + thr_excl;
    #pragma unroll
    for (int k = 0; k < 8; k++) {
        int i = base + k;
        if (i <= NN) g_off[i] = excl;
        if (i < NN) {
            double dsum = (double)(p[k] & 0xFFFFFFFFFFFFULL) * (1.0 / 4294967296.0);
            g_deg[i] = rsqrtf((float)(1.0 + dsum));      // +1 = self loop
        }
        excl += c[k];
    }
}

// ---------------- K3: fill CSR (atomic-free, rank-addressed) ----------------
__global__ void k_fill(const int* __restrict__ rows, const int* __restrict__ cols,
                       const float* __restrict__ ew) {
    int e = blockIdx.x * blockDim.x + threadIdx.x;
    if (e >= NE) return;
    int r = rows[e], c = cols[e];
    float nm = g_deg[r] * ew[e] * g_deg[c];
    unsigned pos = g_off[c] + (unsigned)g_rank[e];
    g_edge[pos] = make_int2(r, __float_as_int(nm));
}

// ---------------- K4: h1 = x @ W1, fp32 accum (f32x2) -> fp16 store ---------
__global__ void __launch_bounds__(128) k_gemm1(const float* __restrict__ x,
                                               const float* __restrict__ W1) {
    __shared__ unsigned long long Ws[DF * (DH / 2)];  // 32KB
    int tid = threadIdx.x;
    const unsigned long long* W64 = reinterpret_cast<const unsigned long long*>(W1);
    for (int i = tid; i < DF * (DH / 2); i += 128) Ws[i] = W64[i];
    __syncthreads();

    int row = blockIdx.x * 128 + tid;
    if (row >= NN) return;

    unsigned long long acc[DH / 2];
    #pragma unroll
    for (int j = 0; j < DH / 2; j++) acc[j] = 0ULL;

    const float4* xr = reinterpret_cast<const float4*>(x + (size_t)row * DF);
    #pragma unroll 1
    for (int k4 = 0; k4 < DF / 4; k4++) {
        float4 xv = __ldg(&xr[k4]);
        float xs4[4] = {xv.x, xv.y, xv.z, xv.w};
        #pragma unroll
        for (int kk = 0; kk < 4; kk++) {
            unsigned long long xp;
            unsigned xb = __float_as_uint(xs4[kk]);
            asm("mov.b64 %0, {%1, %1};" : "=l"(xp) : "r"(xb));
            const unsigned long long* wr = &Ws[(k4 * 4 + kk) * (DH / 2)];
            #pragma unroll
            for (int j = 0; j < DH / 2; j++) {
                asm("fma.rn.f32x2 %0, %1, %2, %0;" : "+l"(acc[j]) : "l"(xp), "l"(wr[j]));
            }
        }
    }
    uint4* hr = reinterpret_cast<uint4*>(&g_h1[(size_t)row * (DH / 2)]);
    #pragma unroll
    for (int q = 0; q < 8; q++) {
        unsigned p[4];
        #pragma unroll
        for (int k = 0; k < 4; k++) {
            unsigned lo, hi;
            asm("mov.b64 {%0, %1}, %2;" : "=r"(lo), "=r"(hi) : "l"(acc[q * 4 + k]));
            __half2 h = __floats2half2_rn(__uint_as_float(lo), __uint_as_float(hi));
            p[k] = *reinterpret_cast<unsigned*>(&h);
        }
        hr[q] = make_uint4(p[0], p[1], p[2], p[3]);
    }
}

// ---------------- K5: gather layer-1 + bias + relu + dot W2 -> h2 ----------
// One warp per node. Edge record via uniform broadcast LDG.64 (L1-resident),
// so per edge: 1 record load + 1 gather + cvt + 2 FFMA; unroll 4 for MLP.
__global__ void __launch_bounds__(256) k_gather1(const float* __restrict__ b1,
                                                 const float* __restrict__ W2) {
    int warp = (blockIdx.x * blockDim.x + threadIdx.x) >> 5;
    int lane = threadIdx.x & 31;
    if (warp >= NN) return;

    unsigned s0 = g_off[warp], s1 = g_off[warp + 1];

    float ax = 0.f, ay = 0.f;
    #pragma unroll 4
    for (unsigned e = s0; e < s1; e++) {
        int2 ed = *(const int2*)&g_edge[e];           // uniform -> broadcast
        float2 h = __half22float2(g_h1[(size_t)ed.x * 32 + lane]);
        float nj = __int_as_float(ed.y);
        ax = fmaf(nj, h.x, ax);
        ay = fmaf(nj, h.y, ay);
    }

    // self loop: norm = dinv[n]^2
    float d = g_deg[warp];
    float d2 = d * d;
    float2 hs = __half22float2(g_h1[(size_t)warp * 32 + lane]);
    ax = fmaf(d2, hs.x, ax);
    ay = fmaf(d2, hs.y, ay);

    float2 bb = reinterpret_cast<const float2*>(b1)[lane];
    float v0 = fmaxf(ax + bb.x, 0.f);
    float v1 = fmaxf(ay + bb.y, 0.f);
    float2 w = reinterpret_cast<const float2*>(W2)[lane];
    float s = v0 * w.x + v1 * w.y;
    #pragma unroll
    for (int off = 16; off > 0; off >>= 1)
        s += __shfl_xor_sync(0xffffffffu, s, off);
    if (lane == 0) g_h2[warp] = s;
}

// ---------------- K6: gather layer-2 -> out ----------------
__global__ void __launch_bounds__(256) k_gather2(float* __restrict__ out,
                                                 const float* __restrict__ b2) {
    int warp = (blockIdx.x * blockDim.x + threadIdx.x) >> 5;
    int lane = threadIdx.x & 31;
    if (warp >= NN) return;
    unsigned s0 = g_off[warp], s1 = g_off[warp + 1];
    float acc = 0.f;
    #pragma unroll 2
    for (unsigned e = s0 + lane; e < s1; e += 32) {
        int2 ed = g_edge[e];
        acc = fmaf(__int_as_float(ed.y), g_h2[ed.x], acc);
    }
    #pragma unroll
    for (int off = 16; off > 0; off >>= 1)
        acc += __shfl_xor_sync(0xffffffffu, acc, off);
    if (lane == 0) {
        float d = g_deg[warp];
        out[warp] = acc + d * d * g_h2[warp] + __ldg(&b2[0]);
    }
}

// ---------------- launch ----------------
extern "C" void kernel_launch(void* const* d_in, const int* in_sizes, int n_in,
                              void* d_out, int out_size) {
    const float* x  = (const float*)d_in[0];
    const int*   ei = (const int*)  d_in[1];
    const float* ew = (const float*)d_in[2];
    const float* W1 = (const float*)d_in[3];
    const float* b1 = (const float*)d_in[4];
    const float* W2 = (const float*)d_in[5];
    const float* b2 = (const float*)d_in[6];
    float* out = (float*)d_out;

    const int* rows = ei;        // sources (gather)
    const int* cols = ei + NE;   // targets (CSR key)

    static cudaStream_t s2 = nullptr;
    static cudaEvent_t evFork = nullptr, evJoin = nullptr;
    if (s2 == nullptr) {
        cudaStreamCreateWithFlags(&s2, cudaStreamNonBlocking);
        cudaEventCreateWithFlags(&evFork, cudaEventDisableTiming);
        cudaEventCreateWithFlags(&evJoin, cudaEventDisableTiming);
    }

    // Fork: GEMM1 (FMA-bound) overlaps the CSR build (LTS/atomic-bound).
    cudaEventRecord(evFork, 0);
    cudaStreamWaitEvent(s2, evFork, 0);
    k_gemm1<<<(NN + 127) / 128, 128, 0, s2>>>(x, W1);
    cudaEventRecord(evJoin, s2);

    // Main chain: CSR build (3 kernels)
    k_deg <<<(NE + 255) / 256, 256>>>(cols, ew);
    k_scan<<<NTILES, 512>>>();
    k_fill<<<(NE + 255) / 256, 256>>>(rows, cols, ew);

    // Join, then the two gather layers.
    cudaStreamWaitEvent(0, evJoin, 0);
    k_gather1<<<(NN * 32 + 255) / 256, 256>>>(b1, W2);
    k_gather2<<<(NN * 32 + 255) / 256, 256>>>(out, b2);
}

// round 11
// speedup vs baseline: 2.1433x; 1.0088x over previous
#include <cuda_runtime.h>
#include <cuda_fp16.h>
#include <cstdint>

#define NN 100000
#define NE 1600000
#define DF 128
#define DH 64
#define STILE 4096
#define NTILES 25   // ceil((NN+1)/STILE); 25 blocks <= 148 SMs -> co-resident

// ---------------- device scratch ----------------
__device__ unsigned long long g_pack[NN];    // hi16: in-count, lo48: ew * 2^32
__device__ float          g_deg[NN];         // d^{-1/2}
__device__ unsigned       g_off[NN + 1];     // CSR offsets (by target)
__device__ unsigned short g_rank[NE];        // edge rank within target node
__device__ unsigned       g_tile[NTILES];    // scan tile sums, bit31 = valid
__device__ int2           g_edge[NE];        // (src row, w*dinv[row] as bits)
__device__ __half2        g_h1[NN * (DH/2)]; // x @ W1, [N,64] fp16, 128B/node
__device__ float          g_h2[NN];          // relu(layer1) . W2 (unscaled)

// ---------------- K1: packed degree+count atomic; rank = old count ----------
__global__ void k_deg(const int* __restrict__ cols, const float* __restrict__ ew) {
    int e = blockIdx.x * blockDim.x + threadIdx.x;
    if (e < NTILES) g_tile[e] = 0u;
    if (e >= NE) return;
    int c = cols[e];
    unsigned long long v =
        (1ULL << 48) | (unsigned long long)((double)ew[e] * 4294967296.0);
    unsigned long long old = atomicAdd(&g_pack[c], v);
    g_rank[e] = (unsigned short)(old >> 48);
}

// ---------------- K2: single-pass scan + dinv + g_pack reset ----------------
__global__ void __launch_bounds__(512) k_scan() {
    __shared__ unsigned warpsum[16];
    __shared__ unsigned s_prefix;
    int t = threadIdx.x;
    int tile = blockIdx.x;
    int base = tile * STILE + t * 8;

    unsigned long long p[8];
    unsigned c[8];
    #pragma unroll
    for (int k = 0; k < 8; k++) {
        int i = base + k;
        p[k] = (i < NN) ? g_pack[i] : 0ULL;
        c[k] = (unsigned)(p[k] >> 48);
    }
    #pragma unroll
    for (int k = 0; k < 8; k++) {
        int i = base + k;
        if (i < NN) g_pack[i] = 0ULL;     // restore invariant for next replay
    }
    unsigned tsum = 0;
    #pragma unroll
    for (int k = 0; k < 8; k++) tsum += c[k];

    unsigned lane = t & 31, wid = t >> 5;
    unsigned scan = tsum;
    #pragma unroll
    for (int off = 1; off < 32; off <<= 1) {
        unsigned v = __shfl_up_sync(0xffffffffu, scan, off);
        if (lane >= off) scan += v;
    }
    if (lane == 31) warpsum[wid] = scan;
    __syncthreads();
    if (wid == 0) {
        unsigned w = (lane < 16) ? warpsum[lane] : 0u;
        #pragma unroll
        for (int off = 1; off < 16; off <<= 1) {
            unsigned v = __shfl_up_sync(0xffffffffu, w, off);
            if (lane >= off) w += v;
        }
        if (lane < 16) warpsum[lane] = w;
    }
    __syncthreads();
    unsigned blocksum = warpsum[15];
    unsigned thr_excl = (scan - tsum) + (wid ? warpsum[wid - 1] : 0u);

    if (t == 0) atomicExch(&g_tile[tile], blocksum | 0x80000000u);

    if (wid == 0) {
        unsigned pre = 0;
        for (int j = (int)lane; j < tile; j += 32) {     // <=1 iter (tile<25)
            unsigned v;
            do { v = atomicOr(&g_tile[j], 0u); } while (!(v & 0x80000000u));
            pre += v & 0x7FFFFFFFu;
        }
        #pragma unroll
        for (int off = 16; off > 0; off >>= 1)
            pre += __shfl_xor_sync(0xffffffffu, pre, off);
        if (lane == 0) s_prefix = pre;
    }
    __syncthreads();

    unsigned excl = s_prefix + thr_excl;
    #pragma unroll
    for (int k = 0; k < 8; k++) {
        int i = base + k;
        if (i <= NN) g_off[i] = excl;
        if (i < NN) {
            double dsum = (double)(p[k] & 0xFFFFFFFFFFFFULL) * (1.0 / 4294967296.0);
            g_deg[i] = rsqrtf((float)(1.0 + dsum));      // +1 = self loop
        }
        excl += c[k];
    }
}

// ---------------- K3: fill CSR. value = w * dinv[row]  (dinv[col] factored
// out of the gather sum, applied warp-uniformly at gather time) ------------
__global__ void k_fill(const int* __restrict__ rows, const int* __restrict__ cols,
                       const float* __restrict__ ew) {
    int e = blockIdx.x * blockDim.x + threadIdx.x;
    if (e >= NE) return;
    int r = rows[e], c = cols[e];
    float nm = ew[e] * g_deg[r];
    unsigned pos = g_off[c] + (unsigned)g_rank[e];
    g_edge[pos] = make_int2(r, __float_as_int(nm));
}

// ---------------- K4: h1 = x @ W1, fp32 accum (f32x2) -> fp16 store ---------
__global__ void __launch_bounds__(128) k_gemm1(const float* __restrict__ x,
                                               const float* __restrict__ W1) {
    __shared__ unsigned long long Ws[DF * (DH / 2)];  // 32KB
    int tid = threadIdx.x;
    const unsigned long long* W64 = reinterpret_cast<const unsigned long long*>(W1);
    for (int i = tid; i < DF * (DH / 2); i += 128) Ws[i] = W64[i];
    __syncthreads();

    int row = blockIdx.x * 128 + tid;
    if (row >= NN) return;

    unsigned long long acc[DH / 2];
    #pragma unroll
    for (int j = 0; j < DH / 2; j++) acc[j] = 0ULL;

    const float4* xr = reinterpret_cast<const float4*>(x + (size_t)row * DF);
    #pragma unroll 1
    for (int k4 = 0; k4 < DF / 4; k4++) {
        float4 xv = __ldg(&xr[k4]);
        float xs4[4] = {xv.x, xv.y, xv.z, xv.w};
        #pragma unroll
        for (int kk = 0; kk < 4; kk++) {
            unsigned long long xp;
            unsigned xb = __float_as_uint(xs4[kk]);
            asm("mov.b64 %0, {%1, %1};" : "=l"(xp) : "r"(xb));
            const unsigned long long* wr = &Ws[(k4 * 4 + kk) * (DH / 2)];
            #pragma unroll
            for (int j = 0; j < DH / 2; j++) {
                asm("fma.rn.f32x2 %0, %1, %2, %0;" : "+l"(acc[j]) : "l"(xp), "l"(wr[j]));
            }
        }
    }
    uint4* hr = reinterpret_cast<uint4*>(&g_h1[(size_t)row * (DH / 2)]);
    #pragma unroll
    for (int q = 0; q < 8; q++) {
        unsigned p[4];
        #pragma unroll
        for (int k = 0; k < 4; k++) {
            unsigned lo, hi;
            asm("mov.b64 {%0, %1}, %2;" : "=r"(lo), "=r"(hi) : "l"(acc[q * 4 + k]));
            __half2 h = __floats2half2_rn(__uint_as_float(lo), __uint_as_float(hi));
            p[k] = *reinterpret_cast<unsigned*>(&h);
        }
        hr[q] = make_uint4(p[0], p[1], p[2], p[3]);
    }
}

// ---------------- K5: gather layer-1 + bias + relu + dot W2 -> h2 ----------
// One warp per node, split into two 16-lane halves; each half handles one
// edge per iteration with a half4 (8B) load per lane -> 2 edges in flight per
// iter, unroll 4 => 8 independent 128B gathers outstanding.
__global__ void __launch_bounds__(256) k_gather1(const float* __restrict__ b1,
                                                 const float* __restrict__ W2) {
    int warp = (blockIdx.x * blockDim.x + threadIdx.x) >> 5;
    int lane = threadIdx.x & 31;
    if (warp >= NN) return;

    unsigned s0 = g_off[warp], s1 = g_off[warp + 1];
    int half = lane >> 4;      // 0 or 1
    int q    = lane & 15;      // feature quad: features 4q..4q+3
    const uint2* h1 = reinterpret_cast<const uint2*>(g_h1);

    float a0 = 0.f, a1 = 0.f, a2 = 0.f, a3 = 0.f;
    #pragma unroll 4
    for (unsigned e = s0; e < s1; e += 2) {
        unsigned idx = e + (unsigned)half;
        if (idx < s1) {
            int2 ed = g_edge[idx];
            uint2 hv = h1[(size_t)ed.x * 16 + q];
            float v = __int_as_float(ed.y);
            float2 fa = __half22float2(*reinterpret_cast<__half2*>(&hv.x));
            float2 fb = __half22float2(*reinterpret_cast<__half2*>(&hv.y));
            a0 = fmaf(v, fa.x, a0);
            a1 = fmaf(v, fa.y, a1);
            a2 = fmaf(v, fb.x, a2);
            a3 = fmaf(v, fb.y, a3);
        }
    }
    // combine the two 16-lane halves
    a0 += __shfl_down_sync(0xffffffffu, a0, 16);
    a1 += __shfl_down_sync(0xffffffffu, a1, 16);
    a2 += __shfl_down_sync(0xffffffffu, a2, 16);
    a3 += __shfl_down_sync(0xffffffffu, a3, 16);

    // lanes 0..15: apply dinv[c], self loop, bias, relu, dot W2
    float d = g_deg[warp];
    uint2 hv = h1[(size_t)warp * 16 + q];
    float2 fa = __half22float2(*reinterpret_cast<__half2*>(&hv.x));
    float2 fb = __half22float2(*reinterpret_cast<__half2*>(&hv.y));
    // agg = d*acc + d^2*h1_self = d*(acc + d*h1_self)
    a0 = d * fmaf(d, fa.x, a0);
    a1 = d * fmaf(d, fa.y, a1);
    a2 = d * fmaf(d, fb.x, a2);
    a3 = d * fmaf(d, fb.y, a3);

    float4 bb = reinterpret_cast<const float4*>(b1)[q];
    float4 ww = reinterpret_cast<const float4*>(W2)[q];
    float s = fmaxf(a0 + bb.x, 0.f) * ww.x
            + fmaxf(a1 + bb.y, 0.f) * ww.y
            + fmaxf(a2 + bb.z, 0.f) * ww.z
            + fmaxf(a3 + bb.w, 0.f) * ww.w;
    #pragma unroll
    for (int off = 8; off > 0; off >>= 1)
        s += __shfl_xor_sync(0xffffffffu, s, off);
    if (lane == 0) g_h2[warp] = s;
}

// ---------------- K6: gather layer-2 -> out ----------------
__global__ void __launch_bounds__(256) k_gather2(float* __restrict__ out,
                                                 const float* __restrict__ b2) {
    int warp = (blockIdx.x * blockDim.x + threadIdx.x) >> 5;
    int lane = threadIdx.x & 31;
    if (warp >= NN) return;
    unsigned s0 = g_off[warp], s1 = g_off[warp + 1];
    float acc = 0.f;
    #pragma unroll 4
    for (unsigned e = s0 + lane; e < s1; e += 32) {
        int2 ed = g_edge[e];
        acc = fmaf(__int_as_float(ed.y), g_h2[ed.x], acc);
    }
    #pragma unroll
    for (int off = 16; off > 0; off >>= 1)
        acc += __shfl_xor_sync(0xffffffffu, acc, off);
    if (lane == 0) {
        float d = g_deg[warp];
        out[warp] = d * fmaf(d, g_h2[warp], acc) + __ldg(&b2[0]);
    }
}

// ---------------- launch ----------------
extern "C" void kernel_launch(void* const* d_in, const int* in_sizes, int n_in,
                              void* d_out, int out_size) {
    const float* x  = (const float*)d_in[0];
    const int*   ei = (const int*)  d_in[1];
    const float* ew = (const float*)d_in[2];
    const float* W1 = (const float*)d_in[3];
    const float* b1 = (const float*)d_in[4];
    const float* W2 = (const float*)d_in[5];
    const float* b2 = (const float*)d_in[6];
    float* out = (float*)d_out;

    const int* rows = ei;        // sources (gather)
    const int* cols = ei + NE;   // targets (CSR key)

    static cudaStream_t s2 = nullptr;
    static cudaEvent_t evFork = nullptr, evJoin = nullptr;
    if (s2 == nullptr) {
        cudaStreamCreateWithFlags(&s2, cudaStreamNonBlocking);
        cudaEventCreateWithFlags(&evFork, cudaEventDisableTiming);
        cudaEventCreateWithFlags(&evJoin, cudaEventDisableTiming);
    }

    // Fork: GEMM1 (FMA-bound) overlaps the CSR build (LTS/atomic-bound).
    cudaEventRecord(evFork, 0);
    cudaStreamWaitEvent(s2, evFork, 0);
    k_gemm1<<<(NN + 127) / 128, 128, 0, s2>>>(x, W1);
    cudaEventRecord(evJoin, s2);

    // Main chain: CSR build (3 kernels)
    k_deg <<<(NE + 255) / 256, 256>>>(cols, ew);
    k_scan<<<NTILES, 512>>>();
    k_fill<<<(NE + 255) / 256, 256>>>(rows, cols, ew);

    // Join, then the two gather layers.
    cudaStreamWaitEvent(0, evJoin, 0);
    k_gather1<<<(NN * 32 + 255) / 256, 256>>>(b1, W2);
    k_gather2<<<(NN * 32 + 255) / 256, 256>>>(out, b2);
}